// round 16
// baseline (speedup 1.0000x reference)
#include <cuda_runtime.h>
#include <cuda_fp16.h>

typedef unsigned int u32;

#define T_STEPS 512
#define BATCH   2048
#define IN_DIM  28
#define H_DIM   64
#define OUT_DIM 10
#define NB      16
#define NTHR    512
#define NCTA    (BATCH / NB)   // 128
#define XS      136            // X row stride in fp16 elems (conflict-free)

static __device__ __forceinline__ float tanh_fast(float x) {
    float y; asm("tanh.approx.f32 %0, %1;" : "=f"(y) : "f"(x)); return y;
}
static __device__ __forceinline__ u32 pkh(__half a, __half b) {
    __half2 t; t.x = a; t.y = b;
    return *reinterpret_cast<u32*>(&t);
}
// pack two f32 into f16x2 {lo, hi}
static __device__ __forceinline__ u32 packf2(float lo, float hi) {
    u32 r;
    asm("cvt.rn.f16x2.f32 %0, %1, %2;" : "=r"(r) : "f"(hi), "f"(lo));
    return r;
}
static __device__ __forceinline__ u32 h2tanh(u32 v) {
    u32 r;
    asm("tanh.approx.f16x2 %0, %1;" : "=r"(r) : "r"(v));
    return r;
}
static __device__ __forceinline__ float lo2f(u32 v) {
    __half2 h = *reinterpret_cast<__half2*>(&v);
    return __low2float(h);
}
static __device__ __forceinline__ float hi2f(u32 v) {
    __half2 h = *reinterpret_cast<__half2*>(&v);
    return __high2float(h);
}
// D = A(f16) * B(f16) + D(f32), m16n8k16
static __device__ __forceinline__ void mma_f16(
    float c[4], const u32 a[4], u32 b0, u32 b1)
{
    asm volatile(
        "mma.sync.aligned.m16n8k16.row.col.f32.f16.f16.f32 "
        "{%0,%1,%2,%3}, {%4,%5,%6,%7}, {%8,%9}, {%0,%1,%2,%3};"
        : "+f"(c[0]), "+f"(c[1]), "+f"(c[2]), "+f"(c[3])
        : "r"(a[0]), "r"(a[1]), "r"(a[2]), "r"(a[3]), "r"(b0), "r"(b1));
}

// Warp-tile per m-tile: M=16 gate rows = [i u0..3 | f u0..3 | g u0..3 | o u0..3].
// i/f/o weight rows and biases pre-scaled by 0.5 so sigma(x)=0.5*tanh(q)+0.5
// with q straight from the MMA.  Hybrid nonlinearity precision:
//   i,f  : one tanh.approx.f16x2 per cell (error enters c, damped by f<1)
//   g, o, tanh(c) : fp32 tanh (these touch h directly -> keep accurate)
// Fused pipeline: warps 0-7 = layer0 step t; warps 8-15 = layer1 step t-1.
// iter t: l0 reads X0[t&1], writes X0[t&1^1] + h1 -> X1[t&1];
//         l1 reads X1[t&1^1], writes h2 -> X1[t&1].  One barrier per iter.

__global__ void __launch_bounds__(NTHR, 1)
lstm_fused(const float* __restrict__ x,
           const float* __restrict__ Wih0, const float* __restrict__ Whh0,
           const float* __restrict__ bih0, const float* __restrict__ bhh0,
           const float* __restrict__ Wih1, const float* __restrict__ Whh1,
           const float* __restrict__ bih1, const float* __restrict__ bhh1,
           const float* __restrict__ Wout, const float* __restrict__ bout,
           float* __restrict__ dout)
{
    __shared__ __half X0[2][NB * XS];
    __shared__ __half X1[2][NB * XS];
    __shared__ float  hbuf[NB * H_DIM];

    const int tid = threadIdx.x;
    const int wd = tid >> 5, lane = tid & 31;
    const int b0 = blockIdx.x * NB;

    for (int i = tid; i < NB * XS; i += NTHR) {
        __half z = __float2half_rn(0.f);
        X0[0][i] = z; X0[1][i] = z; X1[0][i] = z; X1[1][i] = z;
    }
    __syncthreads();

    const int r    = lane >> 2;
    const int cp   = lane & 3;
    const int half = r >> 2;
    const int grp  = wd >> 3;
    const int wg   = wd & 7;

    if (grp == 0) {
        // ================= layer 0 (warps 0-7) =================
        constexpr int KS = 6;
        u32 A[2][KS][4];
#pragma unroll
        for (int mt = 0; mt < 2; mt++) {
            int ubase = 8 * wg + 4 * mt;
#pragma unroll
            for (int ks = 0; ks < KS; ks++)
#pragma unroll
                for (int rg = 0; rg < 4; rg++) {
                    int rl = r + (rg & 1) * 8;
                    int p = rl >> 2;
                    float sc = (p == 2) ? 1.0f : 0.5f;   // i,f,o scaled
                    int g = p * 64 + ubase + (rl & 3);
                    int k = ks * 16 + cp * 2 + (rg >> 1) * 8;
                    float w0 = 0.f, w1 = 0.f;
                    if (k < IN_DIM)      w0 = Wih0[g * IN_DIM + k];
                    else if (k < 92)     w0 = Whh0[g * H_DIM + k - IN_DIM];
                    if (k + 1 < IN_DIM)  w1 = Wih0[g * IN_DIM + k + 1];
                    else if (k + 1 < 92) w1 = Whh0[g * H_DIM + k + 1 - IN_DIM];
                    A[mt][ks][rg] = pkh(__float2half_rn(w0 * sc),
                                        __float2half_rn(w1 * sc));
                }
        }
        float bA[2], bB[2];
        int uu[2];
#pragma unroll
        for (int mt = 0; mt < 2; mt++) {
            uu[mt] = 8 * wg + 4 * mt + (r & 3);
            int gA = (half ? 1 : 0) * 64 + uu[mt];       // i or f: scale 0.5
            int gB = (half ? 3 : 2) * 64 + uu[mt];       // g (no) or o (0.5)
            bA[mt] = 0.5f * (bih0[gA] + bhh0[gA]);
            bB[mt] = (half ? 0.5f : 1.0f) * (bih0[gB] + bhh0[gB]);
        }
        float cst[2][2] = {{0.f, 0.f}, {0.f, 0.f}};

        // x loader: 448 items over 256 grp0 threads
        const int  i1 = tid + 256;
        const bool a1 = (i1 < NB * IN_DIM);
        const int  xb0 = tid / IN_DIM, xk0 = tid % IN_DIM, xo0 = xb0 * XS + xk0;
        const int  xb1 = a1 ? i1 / IN_DIM : 0, xk1 = a1 ? i1 % IN_DIM : 0;
        const int  xo1 = xb1 * XS + xk1;

        X0[0][xo0] = __float2half_rn(
            x[((long long)(b0 + xb0) * T_STEPS) * IN_DIM + xk0]);
        if (a1)
            X0[0][xo1] = __float2half_rn(
                x[((long long)(b0 + xb1) * T_STEPS) * IN_DIM + xk1]);

        for (int t = 0; t <= T_STEPS; t++) {
            __syncthreads();
            if (t >= T_STEPS) continue;
            const int cur = t & 1, oth = cur ^ 1;

            float nx0 = 0.f, nx1 = 0.f;
            if (t + 1 < T_STEPS) {
                nx0 = x[((long long)(b0 + xb0) * T_STEPS + t + 1) * IN_DIM + xk0];
                if (a1)
                    nx1 = x[((long long)(b0 + xb1) * T_STEPS + t + 1) * IN_DIM + xk1];
            }

            float C[2][2][4];
#pragma unroll
            for (int mt = 0; mt < 2; mt++)
#pragma unroll
                for (int nt = 0; nt < 2; nt++) {
                    C[mt][nt][0] = bA[mt]; C[mt][nt][1] = bA[mt];
                    C[mt][nt][2] = bB[mt]; C[mt][nt][3] = bB[mt];
                }
#pragma unroll
            for (int ks = 0; ks < KS; ks++) {
                int kb = ks * 16 + cp * 2;
#pragma unroll
                for (int nt = 0; nt < 2; nt++) {
                    int n = nt * 8 + r;
                    u32 q0 = *reinterpret_cast<const u32*>(&X0[cur][n * XS + kb]);
                    u32 q1 = *reinterpret_cast<const u32*>(&X0[cur][n * XS + kb + 8]);
                    mma_f16(C[0][nt], A[0][ks], q0, q1);
                    mma_f16(C[1][nt], A[1][ks], q0, q1);
                }
            }

            // exchange: (i/2, f/2) -> f16x2 tanh; g, o -> fp32
            u32 pa[2][2];
            float gv[2][2], ov[2][2];
#pragma unroll
            for (int mt = 0; mt < 2; mt++)
#pragma unroll
                for (int nt = 0; nt < 2; nt++) {
                    float s1 = half ? C[mt][nt][0] : C[mt][nt][1];
                    float s2 = half ? C[mt][nt][2] : C[mt][nt][3];
                    float rx1 = __shfl_xor_sync(0xFFFFFFFFu, s1, 16);
                    float rx2 = __shfl_xor_sync(0xFFFFFFFFu, s2, 16);
                    float iv = half ? rx1          : C[mt][nt][0];
                    float fv = half ? C[mt][nt][1] : rx1;
                    float gq = half ? rx2          : C[mt][nt][2];
                    float oq = half ? C[mt][nt][3] : rx2;
                    pa[mt][nt] = packf2(iv, fv);
                    gv[mt][nt] = tanh_fast(gq);
                    ov[mt][nt] = fmaf(0.5f, tanh_fast(oq), 0.5f);
                }
#pragma unroll
            for (int mt = 0; mt < 2; mt++)
#pragma unroll
                for (int nt = 0; nt < 2; nt++)
                    pa[mt][nt] = h2tanh(pa[mt][nt]);
#pragma unroll
            for (int mt = 0; mt < 2; mt++)
#pragma unroll
                for (int nt = 0; nt < 2; nt++) {
                    float i_ = fmaf(0.5f, lo2f(pa[mt][nt]), 0.5f);
                    float f_ = fmaf(0.5f, hi2f(pa[mt][nt]), 0.5f);
                    cst[mt][nt] = fmaf(f_, cst[mt][nt], i_ * gv[mt][nt]);
                    float h = ov[mt][nt] * tanh_fast(cst[mt][nt]);
                    int b = nt * 8 + 2 * cp + half;
                    __half hh = __float2half_rn(h);
                    X0[oth][b * XS + IN_DIM + uu[mt]] = hh;  // h0 recurrent
                    X1[cur][b * XS + uu[mt]]          = hh;  // h1 -> layer1
                }

            if (t + 1 < T_STEPS) {
                X0[oth][xo0] = __float2half_rn(nx0);
                if (a1) X0[oth][xo1] = __float2half_rn(nx1);
            }
        }
    } else {
        // ================= layer 1 (warps 8-15), step t-1 =================
        constexpr int KS = 8;
        u32 A[2][KS][4];
#pragma unroll
        for (int mt = 0; mt < 2; mt++) {
            int ubase = 8 * wg + 4 * mt;
#pragma unroll
            for (int ks = 0; ks < KS; ks++)
#pragma unroll
                for (int rg = 0; rg < 4; rg++) {
                    int rl = r + (rg & 1) * 8;
                    int p = rl >> 2;
                    float sc = (p == 2) ? 1.0f : 0.5f;
                    int g = p * 64 + ubase + (rl & 3);
                    int k = ks * 16 + cp * 2 + (rg >> 1) * 8;
                    float w0 = (k < H_DIM) ? Wih1[g * H_DIM + k]
                                           : Whh1[g * H_DIM + k - H_DIM];
                    float w1 = (k + 1 < H_DIM) ? Wih1[g * H_DIM + k + 1]
                                               : Whh1[g * H_DIM + k + 1 - H_DIM];
                    A[mt][ks][rg] = pkh(__float2half_rn(w0 * sc),
                                        __float2half_rn(w1 * sc));
                }
        }
        float bA[2], bB[2];
        int uu[2];
#pragma unroll
        for (int mt = 0; mt < 2; mt++) {
            uu[mt] = 8 * wg + 4 * mt + (r & 3);
            int gA = (half ? 1 : 0) * 64 + uu[mt];
            int gB = (half ? 3 : 2) * 64 + uu[mt];
            bA[mt] = 0.5f * (bih1[gA] + bhh1[gA]);
            bB[mt] = (half ? 0.5f : 1.0f) * (bih1[gB] + bhh1[gB]);
        }
        float cst[2][2] = {{0.f, 0.f}, {0.f, 0.f}};

        for (int t = 0; t <= T_STEPS; t++) {
            __syncthreads();
            if (t == 0) continue;
            const int cur = t & 1, oth = cur ^ 1;

            float C[2][2][4];
#pragma unroll
            for (int mt = 0; mt < 2; mt++)
#pragma unroll
                for (int nt = 0; nt < 2; nt++) {
                    C[mt][nt][0] = bA[mt]; C[mt][nt][1] = bA[mt];
                    C[mt][nt][2] = bB[mt]; C[mt][nt][3] = bB[mt];
                }
#pragma unroll
            for (int ks = 0; ks < KS; ks++) {
                int kb = ks * 16 + cp * 2;
#pragma unroll
                for (int nt = 0; nt < 2; nt++) {
                    int n = nt * 8 + r;
                    u32 q0 = *reinterpret_cast<const u32*>(&X1[oth][n * XS + kb]);
                    u32 q1 = *reinterpret_cast<const u32*>(&X1[oth][n * XS + kb + 8]);
                    mma_f16(C[0][nt], A[0][ks], q0, q1);
                    mma_f16(C[1][nt], A[1][ks], q0, q1);
                }
            }

            u32 pa[2][2];
            float gv[2][2], ov[2][2];
#pragma unroll
            for (int mt = 0; mt < 2; mt++)
#pragma unroll
                for (int nt = 0; nt < 2; nt++) {
                    float s1 = half ? C[mt][nt][0] : C[mt][nt][1];
                    float s2 = half ? C[mt][nt][2] : C[mt][nt][3];
                    float rx1 = __shfl_xor_sync(0xFFFFFFFFu, s1, 16);
                    float rx2 = __shfl_xor_sync(0xFFFFFFFFu, s2, 16);
                    float iv = half ? rx1          : C[mt][nt][0];
                    float fv = half ? C[mt][nt][1] : rx1;
                    float gq = half ? rx2          : C[mt][nt][2];
                    float oq = half ? C[mt][nt][3] : rx2;
                    pa[mt][nt] = packf2(iv, fv);
                    gv[mt][nt] = tanh_fast(gq);
                    ov[mt][nt] = fmaf(0.5f, tanh_fast(oq), 0.5f);
                }
#pragma unroll
            for (int mt = 0; mt < 2; mt++)
#pragma unroll
                for (int nt = 0; nt < 2; nt++)
                    pa[mt][nt] = h2tanh(pa[mt][nt]);
#pragma unroll
            for (int mt = 0; mt < 2; mt++)
#pragma unroll
                for (int nt = 0; nt < 2; nt++) {
                    float i_ = fmaf(0.5f, lo2f(pa[mt][nt]), 0.5f);
                    float f_ = fmaf(0.5f, hi2f(pa[mt][nt]), 0.5f);
                    cst[mt][nt] = fmaf(f_, cst[mt][nt], i_ * gv[mt][nt]);
                    float h = ov[mt][nt] * tanh_fast(cst[mt][nt]);
                    int b = nt * 8 + 2 * cp + half;
                    X1[cur][b * XS + H_DIM + uu[mt]] = __float2half_rn(h);
                    if (t == T_STEPS)
                        hbuf[b * H_DIM + uu[mt]] = h;
                }
        }
    }
    __syncthreads();

    // epilogue (all 512 threads): r_last + out
    for (int idx = tid; idx < NB * H_DIM; idx += NTHR) {
        int bl = idx >> 6, u2 = idx & 63;
        dout[(long long)BATCH * OUT_DIM + (long long)(b0 + bl) * H_DIM + u2] =
            hbuf[bl * H_DIM + u2];
    }
    for (int i = tid; i < NB * OUT_DIM; i += NTHR) {
        int bl = i / OUT_DIM, o = i % OUT_DIM;
        float s = bout[o];
#pragma unroll
        for (int u2 = 0; u2 < H_DIM; u2++)
            s = fmaf(hbuf[bl * H_DIM + u2], Wout[o * H_DIM + u2], s);
        dout[(long long)(b0 + bl) * OUT_DIM + o] = s;
    }
}

// ---------------------------------------------------------------------------
extern "C" void kernel_launch(void* const* d_in, const int* in_sizes, int n_in,
                              void* d_out, int out_size)
{
    const float* x    = (const float*)d_in[0];
    const float* Wih0 = (const float*)d_in[1];
    const float* Whh0 = (const float*)d_in[2];
    const float* bih0 = (const float*)d_in[3];
    const float* bhh0 = (const float*)d_in[4];
    const float* Wih1 = (const float*)d_in[5];
    const float* Whh1 = (const float*)d_in[6];
    const float* bih1 = (const float*)d_in[7];
    const float* bhh1 = (const float*)d_in[8];
    const float* Wout = (const float*)d_in[9];
    const float* bout = (const float*)d_in[10];
    float* out = (float*)d_out;

    lstm_fused<<<NCTA, NTHR>>>(x, Wih0, Whh0, bih0, bhh0,
                               Wih1, Whh1, bih1, bhh1, Wout, bout, out);
}

// round 17
// speedup vs baseline: 1.5803x; 1.5803x over previous
#include <cuda_runtime.h>
#include <cuda_fp16.h>

typedef unsigned int u32;
typedef unsigned long long u64;

#define T_STEPS 512
#define BATCH   2048
#define IN_DIM  28
#define H_DIM   64
#define OUT_DIM 10
#define NB      16
#define NTHR    512
#define NCTA    (BATCH / NB)   // 128
#define XS      136            // X row stride in fp16 elems

static __device__ __forceinline__ float tanh_fast(float x) {
    float y; asm("tanh.approx.f32 %0, %1;" : "=f"(y) : "f"(x)); return y;
}
static __device__ __forceinline__ u32 pkh(__half a, __half b) {
    __half2 t; t.x = a; t.y = b;
    return *reinterpret_cast<u32*>(&t);
}
static __device__ __forceinline__ u32 h2tanh(u32 v) {
    u32 r;
    asm("tanh.approx.f16x2 %0, %1;" : "=r"(r) : "r"(v));
    return r;
}
static __device__ __forceinline__ float lo2f(u32 v) {
    __half2 h = *reinterpret_cast<__half2*>(&v);
    return __low2float(h);
}
static __device__ __forceinline__ float hi2f(u32 v) {
    __half2 h = *reinterpret_cast<__half2*>(&v);
    return __high2float(h);
}
// storage permutation within each 16-k block: PTX col j stored at s(j) so a
// thread's 4 B-frag cols {2cp,2cp+1,2cp+8,2cp+9} are contiguous (one 8B LDS)
static __device__ __forceinline__ int sperm(int k) {
    return (k & ~15) + 4 * ((k & 7) >> 1) + 2 * ((k >> 3) & 1) + (k & 1);
}
// GO tile: D = A*B + D, f32 accum
static __device__ __forceinline__ void mma_f32(
    float c[4], const u32 a[4], u32 b0, u32 b1)
{
    asm volatile(
        "mma.sync.aligned.m16n8k16.row.col.f32.f16.f16.f32 "
        "{%0,%1,%2,%3}, {%4,%5,%6,%7}, {%8,%9}, {%0,%1,%2,%3};"
        : "+f"(c[0]), "+f"(c[1]), "+f"(c[2]), "+f"(c[3])
        : "r"(a[0]), "r"(a[1]), "r"(a[2]), "r"(a[3]), "r"(b0), "r"(b1));
}
// IF tile: D = A*B + D, f16 accum (output pre-packed f16x2)
static __device__ __forceinline__ void mma_f16a(
    u32 c[2], const u32 a[4], u32 b0, u32 b1)
{
    asm volatile(
        "mma.sync.aligned.m16n8k16.row.col.f16.f16.f16.f16 "
        "{%0,%1}, {%2,%3,%4,%5}, {%6,%7}, {%0,%1};"
        : "+r"(c[0]), "+r"(c[1])
        : "r"(a[0]), "r"(a[1]), "r"(a[2]), "r"(a[3]), "r"(b0), "r"(b1));
}

// Per-warp tiles over units ubase..ubase+7:
//   IF m-tile rows = [i u0..7 | f u0..7]  (f16 accum, i/f/bias pre-scaled 0.5)
//   GO m-tile rows = [g u0..7 | o u0..7]  (f32 accum, o pre-scaled 0.5)
// Thread (r=lane>>2, cp=lane&3) then owns ALL gates of unit ubase+r for
// batches {2cp, 2cp+1} per n-tile -> no shuffle exchange.
// sigma(x) = 0.5*tanh(x/2)+0.5 with x/2 direct from MMA.
// Fused pipeline: warps 0-7 = layer0 step t; warps 8-15 = layer1 step t-1.
// iter t: l0 reads X0[t&1], writes X0[t&1^1] + h1 -> X1[t&1];
//         l1 reads X1[t&1^1], writes h2 -> X1[t&1].  One barrier per iter.

__global__ void __launch_bounds__(NTHR, 1)
lstm_fused(const float* __restrict__ x,
           const float* __restrict__ Wih0, const float* __restrict__ Whh0,
           const float* __restrict__ bih0, const float* __restrict__ bhh0,
           const float* __restrict__ Wih1, const float* __restrict__ Whh1,
           const float* __restrict__ bih1, const float* __restrict__ bhh1,
           const float* __restrict__ Wout, const float* __restrict__ bout,
           float* __restrict__ dout)
{
    __shared__ __align__(16) __half X0[2][NB * XS];
    __shared__ __align__(16) __half X1[2][NB * XS];
    __shared__ float hbuf[NB * H_DIM];

    const int tid = threadIdx.x;
    const int wd = tid >> 5, lane = tid & 31;
    const int b0 = blockIdx.x * NB;

    for (int i = tid; i < NB * XS; i += NTHR) {
        __half z = __float2half_rn(0.f);
        X0[0][i] = z; X0[1][i] = z; X1[0][i] = z; X1[1][i] = z;
    }
    __syncthreads();

    const int r   = lane >> 2;
    const int cp  = lane & 3;
    const int grp = wd >> 3;
    const int wg  = wd & 7;
    const int ub  = 8 * wg;
    const int u   = ub + r;

    if (grp == 0) {
        // ================= layer 0 (warps 0-7) =================
        constexpr int KS = 6;
        u32 Aif[KS][4], Ago[KS][4];
#pragma unroll
        for (int ks = 0; ks < KS; ks++)
#pragma unroll
            for (int rg = 0; rg < 4; rg++) {
                int rl = r + (rg & 1) * 8;
                int un = ub + (rl & 7);
                int k0 = ks * 16 + cp * 2 + (rg >> 1) * 8;
#pragma unroll
                for (int tile = 0; tile < 2; tile++) {
                    int gate = tile == 0 ? (rl < 8 ? 0 : 1) : (rl < 8 ? 2 : 3);
                    float sc = (gate == 2) ? 1.0f : 0.5f;
                    int g = gate * 64 + un;
                    float w0 = 0.f, w1 = 0.f;
                    if (k0 < IN_DIM)      w0 = Wih0[g * IN_DIM + k0];
                    else if (k0 < 92)     w0 = Whh0[g * H_DIM + k0 - IN_DIM];
                    if (k0 + 1 < IN_DIM)  w1 = Wih0[g * IN_DIM + k0 + 1];
                    else if (k0 + 1 < 92) w1 = Whh0[g * H_DIM + k0 + 1 - IN_DIM];
                    u32 pw = pkh(__float2half_rn(w0 * sc), __float2half_rn(w1 * sc));
                    if (tile == 0) Aif[ks][rg] = pw; else Ago[ks][rg] = pw;
                }
            }
        __half bih_ = __float2half_rn(0.5f * (bih0[u] + bhh0[u]));
        __half bfh_ = __float2half_rn(0.5f * (bih0[64 + u] + bhh0[64 + u]));
        const u32  bi2 = pkh(bih_, bih_);
        const u32  bf2 = pkh(bfh_, bfh_);
        const float bg = bih0[128 + u] + bhh0[128 + u];
        const float bo = 0.5f * (bih0[192 + u] + bhh0[192 + u]);

        float cst[4] = {0.f, 0.f, 0.f, 0.f};

        const int sh  = sperm(IN_DIM + u);   // h0 col in X0
        const int s1c = sperm(u);            // h1 col in X1

        // x loader: 448 items over 256 grp0 threads (permuted cols)
        const int  i1 = tid + 256;
        const bool a1 = (i1 < NB * IN_DIM);
        const int  xb0 = tid / IN_DIM, xk0 = tid % IN_DIM;
        const int  xo0 = xb0 * XS + sperm(xk0);
        const int  xb1 = a1 ? i1 / IN_DIM : 0, xk1 = a1 ? i1 % IN_DIM : 0;
        const int  xo1 = xb1 * XS + sperm(xk1);

        X0[0][xo0] = __float2half_rn(
            x[((long long)(b0 + xb0) * T_STEPS) * IN_DIM + xk0]);
        if (a1)
            X0[0][xo1] = __float2half_rn(
                x[((long long)(b0 + xb1) * T_STEPS) * IN_DIM + xk1]);

        for (int t = 0; t <= T_STEPS; t++) {
            __syncthreads();
            if (t >= T_STEPS) continue;
            const int cur = t & 1, oth = cur ^ 1;

            float nx0 = 0.f, nx1 = 0.f;
            if (t + 1 < T_STEPS) {
                nx0 = x[((long long)(b0 + xb0) * T_STEPS + t + 1) * IN_DIM + xk0];
                if (a1)
                    nx1 = x[((long long)(b0 + xb1) * T_STEPS + t + 1) * IN_DIM + xk1];
            }

            u32  Cif[2][2];
            float Cgo[2][4];
#pragma unroll
            for (int nt = 0; nt < 2; nt++) {
                Cif[nt][0] = bi2; Cif[nt][1] = bf2;
                Cgo[nt][0] = bg;  Cgo[nt][1] = bg;
                Cgo[nt][2] = bo;  Cgo[nt][3] = bo;
            }
#pragma unroll
            for (int ks = 0; ks < KS; ks++) {
#pragma unroll
                for (int nt = 0; nt < 2; nt++) {
                    int n = nt * 8 + r;
                    u64 v = *reinterpret_cast<const u64*>(
                        &X0[cur][n * XS + ks * 16 + 4 * cp]);
                    u32 q0 = (u32)v, q1 = (u32)(v >> 32);
                    mma_f16a(Cif[nt], Aif[ks], q0, q1);
                    mma_f32(Cgo[nt], Ago[ks], q0, q1);
                }
            }

#pragma unroll
            for (int nt = 0; nt < 2; nt++) {
                u32 ti = h2tanh(Cif[nt][0]);
                u32 tf = h2tanh(Cif[nt][1]);
                float i0 = fmaf(0.5f, lo2f(ti), 0.5f);
                float i1v = fmaf(0.5f, hi2f(ti), 0.5f);
                float f0 = fmaf(0.5f, lo2f(tf), 0.5f);
                float f1 = fmaf(0.5f, hi2f(tf), 0.5f);
                float g0 = tanh_fast(Cgo[nt][0]);
                float g1 = tanh_fast(Cgo[nt][1]);
                float o0 = fmaf(0.5f, tanh_fast(Cgo[nt][2]), 0.5f);
                float o1 = fmaf(0.5f, tanh_fast(Cgo[nt][3]), 0.5f);
                cst[nt * 2]     = fmaf(f0, cst[nt * 2],     i0  * g0);
                cst[nt * 2 + 1] = fmaf(f1, cst[nt * 2 + 1], i1v * g1);
                float h0 = o0 * tanh_fast(cst[nt * 2]);
                float h1 = o1 * tanh_fast(cst[nt * 2 + 1]);
                int bb = nt * 8 + 2 * cp;
                __half hh0 = __float2half_rn(h0), hh1 = __float2half_rn(h1);
                X0[oth][bb * XS + sh]       = hh0;
                X0[oth][(bb + 1) * XS + sh] = hh1;
                X1[cur][bb * XS + s1c]       = hh0;
                X1[cur][(bb + 1) * XS + s1c] = hh1;
            }

            if (t + 1 < T_STEPS) {
                X0[oth][xo0] = __float2half_rn(nx0);
                if (a1) X0[oth][xo1] = __float2half_rn(nx1);
            }
        }
    } else {
        // ================= layer 1 (warps 8-15), step t-1 =================
        constexpr int KS = 8;
        u32 Aif[KS][4], Ago[KS][4];
#pragma unroll
        for (int ks = 0; ks < KS; ks++)
#pragma unroll
            for (int rg = 0; rg < 4; rg++) {
                int rl = r + (rg & 1) * 8;
                int un = ub + (rl & 7);
                int k0 = ks * 16 + cp * 2 + (rg >> 1) * 8;
#pragma unroll
                for (int tile = 0; tile < 2; tile++) {
                    int gate = tile == 0 ? (rl < 8 ? 0 : 1) : (rl < 8 ? 2 : 3);
                    float sc = (gate == 2) ? 1.0f : 0.5f;
                    int g = gate * 64 + un;
                    float w0 = (k0 < H_DIM) ? Wih1[g * H_DIM + k0]
                                            : Whh1[g * H_DIM + k0 - H_DIM];
                    float w1 = (k0 + 1 < H_DIM) ? Wih1[g * H_DIM + k0 + 1]
                                                : Whh1[g * H_DIM + k0 + 1 - H_DIM];
                    u32 pw = pkh(__float2half_rn(w0 * sc), __float2half_rn(w1 * sc));
                    if (tile == 0) Aif[ks][rg] = pw; else Ago[ks][rg] = pw;
                }
            }
        __half bih_ = __float2half_rn(0.5f * (bih1[u] + bhh1[u]));
        __half bfh_ = __float2half_rn(0.5f * (bih1[64 + u] + bhh1[64 + u]));
        const u32  bi2 = pkh(bih_, bih_);
        const u32  bf2 = pkh(bfh_, bfh_);
        const float bg = bih1[128 + u] + bhh1[128 + u];
        const float bo = 0.5f * (bih1[192 + u] + bhh1[192 + u]);

        float cst[4] = {0.f, 0.f, 0.f, 0.f};
        const int sh = sperm(H_DIM + u);     // h2 col in X1

        for (int t = 0; t <= T_STEPS; t++) {
            __syncthreads();
            if (t == 0) continue;
            const int cur = t & 1, oth = cur ^ 1;

            u32  Cif[2][2];
            float Cgo[2][4];
#pragma unroll
            for (int nt = 0; nt < 2; nt++) {
                Cif[nt][0] = bi2; Cif[nt][1] = bf2;
                Cgo[nt][0] = bg;  Cgo[nt][1] = bg;
                Cgo[nt][2] = bo;  Cgo[nt][3] = bo;
            }
#pragma unroll
            for (int ks = 0; ks < KS; ks++) {
#pragma unroll
                for (int nt = 0; nt < 2; nt++) {
                    int n = nt * 8 + r;
                    u64 v = *reinterpret_cast<const u64*>(
                        &X1[oth][n * XS + ks * 16 + 4 * cp]);
                    u32 q0 = (u32)v, q1 = (u32)(v >> 32);
                    mma_f16a(Cif[nt], Aif[ks], q0, q1);
                    mma_f32(Cgo[nt], Ago[ks], q0, q1);
                }
            }

#pragma unroll
            for (int nt = 0; nt < 2; nt++) {
                u32 ti = h2tanh(Cif[nt][0]);
                u32 tf = h2tanh(Cif[nt][1]);
                float i0 = fmaf(0.5f, lo2f(ti), 0.5f);
                float i1v = fmaf(0.5f, hi2f(ti), 0.5f);
                float f0 = fmaf(0.5f, lo2f(tf), 0.5f);
                float f1 = fmaf(0.5f, hi2f(tf), 0.5f);
                float g0 = tanh_fast(Cgo[nt][0]);
                float g1 = tanh_fast(Cgo[nt][1]);
                float o0 = fmaf(0.5f, tanh_fast(Cgo[nt][2]), 0.5f);
                float o1 = fmaf(0.5f, tanh_fast(Cgo[nt][3]), 0.5f);
                cst[nt * 2]     = fmaf(f0, cst[nt * 2],     i0  * g0);
                cst[nt * 2 + 1] = fmaf(f1, cst[nt * 2 + 1], i1v * g1);
                float h0 = o0 * tanh_fast(cst[nt * 2]);
                float h1 = o1 * tanh_fast(cst[nt * 2 + 1]);
                int bb = nt * 8 + 2 * cp;
                X1[cur][bb * XS + sh]       = __float2half_rn(h0);
                X1[cur][(bb + 1) * XS + sh] = __float2half_rn(h1);
                if (t == T_STEPS) {
                    hbuf[bb * H_DIM + u]       = h0;
                    hbuf[(bb + 1) * H_DIM + u] = h1;
                }
            }
        }
    }
    __syncthreads();

    // epilogue (all 512 threads): r_last + out
    for (int idx = tid; idx < NB * H_DIM; idx += NTHR) {
        int bl = idx >> 6, u2 = idx & 63;
        dout[(long long)BATCH * OUT_DIM + (long long)(b0 + bl) * H_DIM + u2] =
            hbuf[bl * H_DIM + u2];
    }
    for (int i = tid; i < NB * OUT_DIM; i += NTHR) {
        int bl = i / OUT_DIM, o = i % OUT_DIM;
        float s = bout[o];
#pragma unroll
        for (int u2 = 0; u2 < H_DIM; u2++)
            s = fmaf(hbuf[bl * H_DIM + u2], Wout[o * H_DIM + u2], s);
        dout[(long long)(b0 + bl) * OUT_DIM + o] = s;
    }
}

// ---------------------------------------------------------------------------
extern "C" void kernel_launch(void* const* d_in, const int* in_sizes, int n_in,
                              void* d_out, int out_size)
{
    const float* x    = (const float*)d_in[0];
    const float* Wih0 = (const float*)d_in[1];
    const float* Whh0 = (const float*)d_in[2];
    const float* bih0 = (const float*)d_in[3];
    const float* bhh0 = (const float*)d_in[4];
    const float* Wih1 = (const float*)d_in[5];
    const float* Whh1 = (const float*)d_in[6];
    const float* bih1 = (const float*)d_in[7];
    const float* bhh1 = (const float*)d_in[8];
    const float* Wout = (const float*)d_in[9];
    const float* bout = (const float*)d_in[10];
    float* out = (float*)d_out;

    lstm_fused<<<NCTA, NTHR>>>(x, Wih0, Whh0, bih0, bhh0,
                               Wih1, Whh1, bih1, bhh1, Wout, bout, out);
}